// round 15
// baseline (speedup 1.0000x reference)
#include <cuda_runtime.h>
#include <cuda_fp16.h>
#include <math.h>
#include <cstdint>

#define B_    4
#define N_    2048
#define DIN_  512
#define DOUT_ 512
#define H_    8
#define HD_   64

// ---------------- device scratch (all single fp16) ----------------
__device__ __half g_x[B_*N_*DIN_];
__device__ __half g_w[3*DOUT_*DIN_];
__device__ __half g_Q[B_*H_*N_*HD_];
__device__ __half g_K[B_*H_*N_*HD_];
__device__ __half g_V[B_*H_*N_*HD_];
__device__ uint32_t g_mbits[(size_t)B_*N_*N_/32];

__device__ __forceinline__ uint32_t smem_u32(const void* p) {
    uint32_t a;
    asm("{ .reg .u64 t; cvta.to.shared.u64 t, %1; cvt.u32.u64 %0, t; }" : "=r"(a) : "l"(p));
    return a;
}
__device__ __forceinline__ float2 h2f2(uint32_t u) {
    __half2 h = *(__half2*)&u;
    return __half22float2(h);
}
#define CP16(saddr, gptr) \
    asm volatile("cp.async.cg.shared.global [%0], [%1], 16;" :: "r"(saddr), "l"(gptr))
#define CP_COMMIT() asm volatile("cp.async.commit_group;")
#define CP_WAIT0()  asm volatile("cp.async.wait_group 0;")
#define CP_WAIT1()  asm volatile("cp.async.wait_group 1;")

#define LDSM4(r0,r1,r2,r3,addr) \
    asm volatile("ldmatrix.sync.aligned.m8n8.x4.shared.b16 {%0,%1,%2,%3}, [%4];" \
        : "=r"(r0),"=r"(r1),"=r"(r2),"=r"(r3) : "r"(addr))
#define LDSM4T(r0,r1,r2,r3,addr) \
    asm volatile("ldmatrix.sync.aligned.m8n8.x4.trans.shared.b16 {%0,%1,%2,%3}, [%4];" \
        : "=r"(r0),"=r"(r1),"=r"(r2),"=r"(r3) : "r"(addr))
#define MMA16816(c, a0,a1,a2,a3, b0,b1) \
    asm volatile("mma.sync.aligned.m16n8k16.row.col.f32.f16.f16.f32 " \
        "{%0,%1,%2,%3}, {%4,%5,%6,%7}, {%8,%9}, {%0,%1,%2,%3};" \
        : "+f"((c)[0]),"+f"((c)[1]),"+f"((c)[2]),"+f"((c)[3]) \
        : "r"(a0),"r"(a1),"r"(a2),"r"(a3), "r"(b0),"r"(b1))
// fp16-accumulator MMA (PV partials; potential 2x rate)
#define MMA16816H(c, a0,a1,a2,a3, b0,b1) \
    asm volatile("mma.sync.aligned.m16n8k16.row.col.f16.f16.f16.f16 " \
        "{%0,%1}, {%2,%3,%4,%5}, {%6,%7}, {%0,%1};" \
        : "+r"((c)[0]),"+r"((c)[1]) \
        : "r"(a0),"r"(a1),"r"(a2),"r"(a3), "r"(b0),"r"(b1))

// cvt two fp32 -> packed fp16x2 (lo, hi)
#define CVTF16X2(d, hi, lo) \
    asm("cvt.rn.f16x2.f32 %0, %1, %2;" : "=r"(d) : "f"(hi), "f"(lo))
// packed fp16 2^x
#define EX2H2(d, a) \
    asm("ex2.approx.f16x2 %0, %1;" : "=r"(d) : "r"(a))

// ---------------- prep kernels ----------------
__global__ __launch_bounds__(256) void prep_x(const float* __restrict__ x) {
    int i = blockIdx.x * 256 + threadIdx.x;
    float4 v = ((const float4*)x)[i];
    ((__half2*)g_x)[2*i]   = __floats2half2_rn(v.x, v.y);
    ((__half2*)g_x)[2*i+1] = __floats2half2_rn(v.z, v.w);
}
__global__ __launch_bounds__(256) void prep_w(const float* __restrict__ Wq,
                                              const float* __restrict__ Wk,
                                              const float* __restrict__ Wv) {
    int i = blockIdx.x * 256 + threadIdx.x;
    int sel = i >> 16, j = i & 65535;
    const float* src = (sel == 0) ? Wq : (sel == 1) ? Wk : Wv;
    float4 v = ((const float4*)src)[j];
    ((__half2*)g_w)[2*i]   = __floats2half2_rn(v.x, v.y);
    ((__half2*)g_w)[2*i+1] = __floats2half2_rn(v.z, v.w);
}
__global__ __launch_bounds__(256) void pack_mask(const int* __restrict__ m) {
    int i = blockIdx.x * 256 + threadIdx.x;
    uint32_t bal = __ballot_sync(0xffffffffu, m[i] != 0);
    if ((threadIdx.x & 31) == 0) g_mbits[i >> 5] = bal;
}

// ---------------- projection GEMM: 3-stage cp.async pipeline (R13) ----------------
#define PROJ_SMEM 61440

__global__ __launch_bounds__(256, 2) void proj_kernel(
    const float* __restrict__ bq, const float* __restrict__ bk,
    const float* __restrict__ bv)
{
    extern __shared__ __align__(16) char sm[];
    const uint32_t smb = smem_u32(sm);
    const int tid = threadIdx.x, wid = tid >> 5, lane = tid & 31;
    const int sel = blockIdx.z;
    const int m0 = blockIdx.x * 128, o0 = blockIdx.y * 128;
    const int wm = (wid & 3) * 32, wn = (wid >> 2) * 64;
    const float* bias = (sel == 0) ? bq : (sel == 1) ? bk : bv;

    const int row1 = tid >> 2, c8 = (tid & 3) * 8;
    const int row2 = row1 + 64;
    const __half* srcA = g_x + (size_t)m0 * DIN_ + c8;
    const __half* srcB = g_w + (size_t)sel * (DOUT_*DIN_) + (size_t)o0 * DIN_ + c8;
    const uint32_t so1 = (uint32_t)(row1 * 40 + c8) * 2;
    const uint32_t so2 = (uint32_t)(row2 * 40 + c8) * 2;
    const size_t g1 = (size_t)row1 * DIN_, g2 = (size_t)row2 * DIN_;

    const uint32_t tA = (uint32_t)((((lane & 7) + ((lane >> 3) & 1) * 8) * 40 + ((lane >> 4) & 1) * 8) * 2);
    const uint32_t tB = (uint32_t)((((lane & 7) + ((lane >> 4) & 1) * 8) * 40 + ((lane >> 3) & 1) * 8) * 2);

    float acc[2][8][4] = {};

    #pragma unroll
    for (int st = 0; st < 2; st++) {
        const uint32_t sb = smb + st * 20480;
        const size_t ko = (size_t)st * 32;
        CP16(sb +         so1, srcA + g1 + ko); CP16(sb +         so2, srcA + g2 + ko);
        CP16(sb + 10240 + so1, srcB + g1 + ko); CP16(sb + 10240 + so2, srcB + g2 + ko);
        CP_COMMIT();
    }

    for (int ck = 0; ck < 16; ck++) {
        if (ck == 15) { CP_WAIT0(); } else { CP_WAIT1(); }
        __syncthreads();

        if (ck < 14) {
            const uint32_t nb = smb + ((ck + 2) % 3) * 20480;
            const size_t ko = (size_t)(ck + 2) * 32;
            CP16(nb +         so1, srcA + g1 + ko); CP16(nb +         so2, srcA + g2 + ko);
            CP16(nb + 10240 + so1, srcB + g1 + ko); CP16(nb + 10240 + so2, srcB + g2 + ko);
            CP_COMMIT();
        }

        const uint32_t cb = smb + (ck % 3) * 20480;
        const uint32_t Ah = cb, Bh = cb + 10240;
        #pragma unroll
        for (int kk = 0; kk < 2; kk++) {
            uint32_t ah[2][4];
            #pragma unroll
            for (int mt = 0; mt < 2; mt++) {
                const uint32_t ao = tA + (uint32_t)(((wm + mt*16) * 40 + kk*16) * 2);
                LDSM4(ah[mt][0], ah[mt][1], ah[mt][2], ah[mt][3], Ah + ao);
            }
            #pragma unroll
            for (int jn = 0; jn < 4; jn++) {
                const uint32_t bo = tB + (uint32_t)(((wn + jn*16) * 40 + kk*16) * 2);
                uint32_t b0,b1,b2,b3;
                LDSM4(b0,b1,b2,b3, Bh + bo);
                #pragma unroll
                for (int mt = 0; mt < 2; mt++) {
                    MMA16816(acc[mt][2*jn],   ah[mt][0],ah[mt][1],ah[mt][2],ah[mt][3], b0,b1);
                    MMA16816(acc[mt][2*jn+1], ah[mt][0],ah[mt][1],ah[mt][2],ah[mt][3], b2,b3);
                }
            }
        }
    }

    const int r0 = lane >> 2, c0 = (lane & 3) * 2;
    const int hglob = (o0 + wn) >> 6;
    const float scale = (sel == 0) ? 0.125f * 1.4426950408889634f : 1.0f;
    __half* outp = (sel == 0) ? g_Q : (sel == 1) ? g_K : g_V;

    float bb[8][2];
    #pragma unroll
    for (int j8 = 0; j8 < 8; j8++) {
        bb[j8][0] = bias[o0 + wn + j8*8 + c0];
        bb[j8][1] = bias[o0 + wn + j8*8 + c0 + 1];
    }

    #pragma unroll
    for (int mt = 0; mt < 2; mt++) {
        #pragma unroll
        for (int ri = 0; ri < 2; ri++) {
            const int m = m0 + wm + mt*16 + r0 + ri*8;
            const int b = m >> 11, n = m & (N_ - 1);
            __half* dh = outp + (((size_t)b*H_ + hglob)*N_ + n)*HD_ + c0;
            #pragma unroll
            for (int j8 = 0; j8 < 8; j8++) {
                float y0 = (acc[mt][j8][ri*2]   + bb[j8][0]) * scale;
                float y1 = (acc[mt][j8][ri*2+1] + bb[j8][1]) * scale;
                *(__half2*)(dh + j8*8) = __floats2half2_rn(y0, y1);
            }
        }
    }
}

// ---------------- flash attention: fp16-accum PV partials, per-tile merge ----------------
#define ATTN_SMEM 55296   // 3 stages * (K 9216 + V 9216)

__global__ __launch_bounds__(128, 4) void attn_kernel(float* __restrict__ out)
{
    extern __shared__ __align__(16) char sm[];
    const uint32_t smb = smem_u32(sm);
    const int tid = threadIdx.x, wid = tid >> 5, lane = tid & 31;
    const int q0 = blockIdx.x * 64;
    const int h = blockIdx.y, b = blockIdx.z;
    const size_t base = ((size_t)b*H_ + h) * N_ * HD_;
    const int r0 = lane >> 2, c0 = (lane & 3) * 2;

    // ---- persistent Q fragments (pre-scaled by log2e/8 in proj)
    uint32_t qf[4][4];
    {
        const __half* qh = g_Q + base + (size_t)(q0 + wid*16)*HD_;
        #pragma unroll
        for (int k = 0; k < 4; k++) {
            const int off = r0*64 + k*16 + c0;
            qf[k][0] = *(const uint32_t*)(qh + off);
            qf[k][1] = *(const uint32_t*)(qh + off + 8*64);
            qf[k][2] = *(const uint32_t*)(qh + off + 8);
            qf[k][3] = *(const uint32_t*)(qh + off + 8*64 + 8);
        }
    }

    // cp.async mapping
    uint32_t sA[4]; uint32_t gOf[4];
    #pragma unroll
    for (int j = 0; j < 4; j++) {
        const int idx = tid + j*128;
        const int row = idx >> 3, cc8 = (idx & 7) * 8;
        sA[j]  = (uint32_t)(row*72 + cc8) * 2;
        gOf[j] = (uint32_t)(row*64 + cc8);
    }
    const __half* gK = g_K + base;
    const __half* gV = g_V + base;

    #pragma unroll
    for (int st = 0; st < 2; st++) {
        const uint32_t sb = smb + st * 18432;
        const uint32_t ko = (uint32_t)st * 4096;
        #pragma unroll
        for (int j = 0; j < 4; j++) {
            CP16(sb + sA[j],        gK + ko + gOf[j]);
            CP16(sb + 9216 + sA[j], gV + ko + gOf[j]);
        }
        CP_COMMIT();
    }

    const uint32_t* m0p = g_mbits + ((size_t)b*N_ + q0 + wid*16 + r0) * 64;
    const uint32_t* m1p = m0p + 8*64;

    float o_acc[8][4] = {};
    float l_acc[4] = {};
    const uint32_t ONES = 0x3C003C00u;

    const uint32_t tK = (uint32_t)(((((lane>>4)&1)*8 + (lane&7))*72 + ((lane>>3)&1)*8) * 2);
    const uint32_t tV = (uint32_t)(((((lane>>3)&1)*8 + (lane&7))*72 + ((lane>>4)&1)*8) * 2);

    for (int kt = 0; kt < 32; kt++) {
        if (kt == 31) { CP_WAIT0(); } else { CP_WAIT1(); }
        __syncthreads();

        const uint2 w0 = *(const uint2*)(m0p + kt*2);
        const uint2 w1 = *(const uint2*)(m1p + kt*2);

        if (kt < 30) {
            const uint32_t nb = smb + ((kt + 2) % 3) * 18432;
            const uint32_t koff = (uint32_t)(kt + 2) * 4096;
            #pragma unroll
            for (int j = 0; j < 4; j++) {
                CP16(nb + sA[j],        gK + koff + gOf[j]);
                CP16(nb + 9216 + sA[j], gV + koff + gOf[j]);
            }
            CP_COMMIT();
        }

        const uint32_t cb = smb + (kt % 3) * 18432;

        // ---- S = Q K^T (fp32 accum: precision-critical)
        float s[8][4] = {};
        {
            const uint32_t Kh = cb;
            #pragma unroll
            for (int k = 0; k < 4; k++) {
                #pragma unroll
                for (int jp = 0; jp < 4; jp++) {
                    const uint32_t addr = tK + jp*2304 + k*32;
                    uint32_t h0,h1,h2,h3;
                    LDSM4(h0,h1,h2,h3, Kh + addr);
                    MMA16816(s[2*jp],   qf[k][0],qf[k][1],qf[k][2],qf[k][3], h0,h1);
                    MMA16816(s[2*jp+1], qf[k][0],qf[k][1],qf[k][2],qf[k][3], h2,h3);
                }
            }
        }

        // ---- softmax: packed fp16 ex2 + bitwise mask
        uint32_t pa[8][2];
        #pragma unroll
        for (int j = 0; j < 8; j++) {
            const uint32_t wa = (j < 4) ? w0.x : w0.y;
            const uint32_t wb = (j < 4) ? w1.x : w1.y;
            const int sh = (j*8 + c0) & 31;
            uint32_t q01, q23, e01, e23;
            CVTF16X2(q01, s[j][1], s[j][0]);
            CVTF16X2(q23, s[j][3], s[j][2]);
            EX2H2(e01, q01);
            EX2H2(e23, q23);
            const uint32_t m01 = ((wa >> sh) & 1u) * 0x0000FFFFu
                               | ((wa >> (sh+1)) & 1u) * 0xFFFF0000u;
            const uint32_t m23 = ((wb >> sh) & 1u) * 0x0000FFFFu
                               | ((wb >> (sh+1)) & 1u) * 0xFFFF0000u;
            pa[j][0] = e01 & m01;
            pa[j][1] = e23 & m23;
        }

        // ---- PV in fp16 partial accumulators (per-tile, merged to fp32 below)
        {
            const uint32_t Vh = cb + 9216;
            uint32_t o16[8][2];
            #pragma unroll
            for (int j = 0; j < 8; j++) { o16[j][0] = 0u; o16[j][1] = 0u; }

            #pragma unroll
            for (int t = 0; t < 4; t++) {
                const uint32_t a0 = pa[2*t][0],   a1 = pa[2*t][1];
                const uint32_t a2 = pa[2*t+1][0], a3 = pa[2*t+1][1];
                MMA16816(l_acc, a0,a1,a2,a3, ONES, ONES);   // exact l in fp32
                #pragma unroll
                for (int jp = 0; jp < 4; jp++) {
                    const uint32_t addr = tV + t*2304 + jp*32;
                    uint32_t v0,v1,v2,v3;
                    LDSM4T(v0,v1,v2,v3, Vh + addr);
                    MMA16816H(o16[2*jp],   a0,a1,a2,a3, v0,v1);
                    MMA16816H(o16[2*jp+1], a0,a1,a2,a3, v2,v3);
                }
            }
            // merge tile partials into fp32 master accumulators
            #pragma unroll
            for (int j = 0; j < 8; j++) {
                float2 u = h2f2(o16[j][0]);
                float2 v = h2f2(o16[j][1]);
                o_acc[j][0] += u.x; o_acc[j][1] += u.y;
                o_acc[j][2] += v.x; o_acc[j][3] += v.y;
            }
        }
    }

    const float inv0 = 1.0f / l_acc[0], inv1 = 1.0f / l_acc[2];

    const int row0 = q0 + wid*16 + r0;
    float* d0 = out + ((size_t)b*N_ + row0) * DOUT_ + h*HD_ + c0;
    float* d1 = d0 + 8 * DOUT_;
    #pragma unroll
    for (int jo = 0; jo < 8; jo++) {
        float a0 = o_acc[jo][0] * inv0, a1 = o_acc[jo][1] * inv0;
        float a2 = o_acc[jo][2] * inv1, a3 = o_acc[jo][3] * inv1;
        float2 u0, u1;
        u0.x = (a0 > 0.f) ? a0 : expm1f(a0);
        u0.y = (a1 > 0.f) ? a1 : expm1f(a1);
        u1.x = (a2 > 0.f) ? a2 : expm1f(a2);
        u1.y = (a3 > 0.f) ? a3 : expm1f(a3);
        *(float2*)(d0 + jo*8) = u0;
        *(float2*)(d1 + jo*8) = u1;
    }
}

// ---------------- launch ----------------
extern "C" void kernel_launch(void* const* d_in, const int* in_sizes, int n_in,
                              void* d_out, int out_size)
{
    const float* x  = (const float*)d_in[0];
    const float* Wq = (const float*)d_in[1];
    const float* bq = (const float*)d_in[2];
    const float* Wk = (const float*)d_in[3];
    const float* bk = (const float*)d_in[4];
    const float* Wv = (const float*)d_in[5];
    const float* bv = (const float*)d_in[6];
    const int*   mask = (const int*)d_in[7];
    float* out = (float*)d_out;

    prep_x<<<(B_*N_*DIN_/4)/256, 256>>>(x);
    prep_w<<<(3*DOUT_*DIN_/4)/256, 256>>>(Wq, Wk, Wv);
    pack_mask<<<(B_*N_*N_)/256, 256>>>(mask);

    cudaFuncSetAttribute(proj_kernel, cudaFuncAttributeMaxDynamicSharedMemorySize, PROJ_SMEM);
    proj_kernel<<<dim3((B_*N_)/128, DOUT_/128, 3), 256, PROJ_SMEM>>>(bq, bk, bv);

    cudaFuncSetAttribute(attn_kernel, cudaFuncAttributeMaxDynamicSharedMemorySize, ATTN_SMEM);
    attn_kernel<<<dim3(N_/64, H_, B_), 128, ATTN_SMEM>>>(out);
}

// round 16
// speedup vs baseline: 1.2170x; 1.2170x over previous
#include <cuda_runtime.h>
#include <cuda_fp16.h>
#include <math.h>
#include <cstdint>

#define B_    4
#define N_    2048
#define DIN_  512
#define DOUT_ 512
#define H_    8
#define HD_   64

// ---------------- device scratch (all single fp16) ----------------
__device__ __half g_x[B_*N_*DIN_];
__device__ __half g_w[3*DOUT_*DIN_];
__device__ __half g_Q[B_*H_*N_*HD_];
__device__ __half g_K[B_*H_*N_*HD_];
__device__ __half g_V[B_*H_*N_*HD_];
__device__ uint32_t g_mbits[(size_t)B_*N_*N_/32];

__device__ __forceinline__ uint32_t smem_u32(const void* p) {
    uint32_t a;
    asm("{ .reg .u64 t; cvta.to.shared.u64 t, %1; cvt.u32.u64 %0, t; }" : "=r"(a) : "l"(p));
    return a;
}
#define CP16(saddr, gptr) \
    asm volatile("cp.async.cg.shared.global [%0], [%1], 16;" :: "r"(saddr), "l"(gptr))
#define CP_COMMIT() asm volatile("cp.async.commit_group;")
#define CP_WAIT0()  asm volatile("cp.async.wait_group 0;")
#define CP_WAIT1()  asm volatile("cp.async.wait_group 1;")

#define LDSM4(r0,r1,r2,r3,addr) \
    asm volatile("ldmatrix.sync.aligned.m8n8.x4.shared.b16 {%0,%1,%2,%3}, [%4];" \
        : "=r"(r0),"=r"(r1),"=r"(r2),"=r"(r3) : "r"(addr))
#define LDSM4T(r0,r1,r2,r3,addr) \
    asm volatile("ldmatrix.sync.aligned.m8n8.x4.trans.shared.b16 {%0,%1,%2,%3}, [%4];" \
        : "=r"(r0),"=r"(r1),"=r"(r2),"=r"(r3) : "r"(addr))
#define MMA16816(c, a0,a1,a2,a3, b0,b1) \
    asm volatile("mma.sync.aligned.m16n8k16.row.col.f32.f16.f16.f32 " \
        "{%0,%1,%2,%3}, {%4,%5,%6,%7}, {%8,%9}, {%0,%1,%2,%3};" \
        : "+f"((c)[0]),"+f"((c)[1]),"+f"((c)[2]),"+f"((c)[3]) \
        : "r"(a0),"r"(a1),"r"(a2),"r"(a3), "r"(b0),"r"(b1))

// cvt two fp32 -> packed fp16x2 (lo, hi)
#define CVTF16X2(d, hi, lo) \
    asm("cvt.rn.f16x2.f32 %0, %1, %2;" : "=r"(d) : "f"(hi), "f"(lo))
// packed fp16 2^x
#define EX2H2(d, a) \
    asm("ex2.approx.f16x2 %0, %1;" : "=r"(d) : "r"(a))

// ---------------- fused prep: mask packing + x/w fp16 conversion ----------------
// Grid layout: [0, 16384)           -> pack_mask (4 ballots per block, 1024 ints)
//              [16384, 16384+4096)  -> prep_x    (256 float4 per block)
//              [20480, 20480+768)   -> prep_w    (256 float4 per block)
#define PREP_MASK_BLOCKS 16384
#define PREP_X_BLOCKS    4096
#define PREP_W_BLOCKS    768
#define PREP_TOTAL_BLOCKS (PREP_MASK_BLOCKS + PREP_X_BLOCKS + PREP_W_BLOCKS)

__global__ __launch_bounds__(256) void prep_all(
    const float* __restrict__ x,
    const float* __restrict__ Wq, const float* __restrict__ Wk,
    const float* __restrict__ Wv, const int* __restrict__ m)
{
    const int bid = blockIdx.x, tid = threadIdx.x;
    if (bid < PREP_MASK_BLOCKS) {
        const int base = bid * 1024;
        #pragma unroll
        for (int k = 0; k < 4; k++) {
            const int i = base + k*256 + tid;
            uint32_t bal = __ballot_sync(0xffffffffu, m[i] != 0);
            if ((tid & 31) == 0) g_mbits[i >> 5] = bal;
        }
    } else if (bid < PREP_MASK_BLOCKS + PREP_X_BLOCKS) {
        const int i = (bid - PREP_MASK_BLOCKS) * 256 + tid;
        float4 v = ((const float4*)x)[i];
        ((__half2*)g_x)[2*i]   = __floats2half2_rn(v.x, v.y);
        ((__half2*)g_x)[2*i+1] = __floats2half2_rn(v.z, v.w);
    } else {
        const int i = (bid - PREP_MASK_BLOCKS - PREP_X_BLOCKS) * 256 + tid;
        const int sel = i >> 16, j = i & 65535;
        const float* src = (sel == 0) ? Wq : (sel == 1) ? Wk : Wv;
        float4 v = ((const float4*)src)[j];
        ((__half2*)g_w)[2*i]   = __floats2half2_rn(v.x, v.y);
        ((__half2*)g_w)[2*i+1] = __floats2half2_rn(v.z, v.w);
    }
}

// ---------------- projection GEMM: 3-stage cp.async pipeline (R13) ----------------
#define PROJ_SMEM 61440

__global__ __launch_bounds__(256, 2) void proj_kernel(
    const float* __restrict__ bq, const float* __restrict__ bk,
    const float* __restrict__ bv)
{
    extern __shared__ __align__(16) char sm[];
    const uint32_t smb = smem_u32(sm);
    const int tid = threadIdx.x, wid = tid >> 5, lane = tid & 31;
    const int sel = blockIdx.z;
    const int m0 = blockIdx.x * 128, o0 = blockIdx.y * 128;
    const int wm = (wid & 3) * 32, wn = (wid >> 2) * 64;
    const float* bias = (sel == 0) ? bq : (sel == 1) ? bk : bv;

    const int row1 = tid >> 2, c8 = (tid & 3) * 8;
    const int row2 = row1 + 64;
    const __half* srcA = g_x + (size_t)m0 * DIN_ + c8;
    const __half* srcB = g_w + (size_t)sel * (DOUT_*DIN_) + (size_t)o0 * DIN_ + c8;
    const uint32_t so1 = (uint32_t)(row1 * 40 + c8) * 2;
    const uint32_t so2 = (uint32_t)(row2 * 40 + c8) * 2;
    const size_t g1 = (size_t)row1 * DIN_, g2 = (size_t)row2 * DIN_;

    const uint32_t tA = (uint32_t)((((lane & 7) + ((lane >> 3) & 1) * 8) * 40 + ((lane >> 4) & 1) * 8) * 2);
    const uint32_t tB = (uint32_t)((((lane & 7) + ((lane >> 4) & 1) * 8) * 40 + ((lane >> 3) & 1) * 8) * 2);

    float acc[2][8][4] = {};

    #pragma unroll
    for (int st = 0; st < 2; st++) {
        const uint32_t sb = smb + st * 20480;
        const size_t ko = (size_t)st * 32;
        CP16(sb +         so1, srcA + g1 + ko); CP16(sb +         so2, srcA + g2 + ko);
        CP16(sb + 10240 + so1, srcB + g1 + ko); CP16(sb + 10240 + so2, srcB + g2 + ko);
        CP_COMMIT();
    }

    for (int ck = 0; ck < 16; ck++) {
        if (ck == 15) { CP_WAIT0(); } else { CP_WAIT1(); }
        __syncthreads();

        if (ck < 14) {
            const uint32_t nb = smb + ((ck + 2) % 3) * 20480;
            const size_t ko = (size_t)(ck + 2) * 32;
            CP16(nb +         so1, srcA + g1 + ko); CP16(nb +         so2, srcA + g2 + ko);
            CP16(nb + 10240 + so1, srcB + g1 + ko); CP16(nb + 10240 + so2, srcB + g2 + ko);
            CP_COMMIT();
        }

        const uint32_t cb = smb + (ck % 3) * 20480;
        const uint32_t Ah = cb, Bh = cb + 10240;
        #pragma unroll
        for (int kk = 0; kk < 2; kk++) {
            uint32_t ah[2][4];
            #pragma unroll
            for (int mt = 0; mt < 2; mt++) {
                const uint32_t ao = tA + (uint32_t)(((wm + mt*16) * 40 + kk*16) * 2);
                LDSM4(ah[mt][0], ah[mt][1], ah[mt][2], ah[mt][3], Ah + ao);
            }
            #pragma unroll
            for (int jn = 0; jn < 4; jn++) {
                const uint32_t bo = tB + (uint32_t)(((wn + jn*16) * 40 + kk*16) * 2);
                uint32_t b0,b1,b2,b3;
                LDSM4(b0,b1,b2,b3, Bh + bo);
                #pragma unroll
                for (int mt = 0; mt < 2; mt++) {
                    MMA16816(acc[mt][2*jn],   ah[mt][0],ah[mt][1],ah[mt][2],ah[mt][3], b0,b1);
                    MMA16816(acc[mt][2*jn+1], ah[mt][0],ah[mt][1],ah[mt][2],ah[mt][3], b2,b3);
                }
            }
        }
    }

    const int r0 = lane >> 2, c0 = (lane & 3) * 2;
    const int hglob = (o0 + wn) >> 6;
    const float scale = (sel == 0) ? 0.125f * 1.4426950408889634f : 1.0f;
    __half* outp = (sel == 0) ? g_Q : (sel == 1) ? g_K : g_V;

    float bb[8][2];
    #pragma unroll
    for (int j8 = 0; j8 < 8; j8++) {
        bb[j8][0] = bias[o0 + wn + j8*8 + c0];
        bb[j8][1] = bias[o0 + wn + j8*8 + c0 + 1];
    }

    #pragma unroll
    for (int mt = 0; mt < 2; mt++) {
        #pragma unroll
        for (int ri = 0; ri < 2; ri++) {
            const int m = m0 + wm + mt*16 + r0 + ri*8;
            const int b = m >> 11, n = m & (N_ - 1);
            __half* dh = outp + (((size_t)b*H_ + hglob)*N_ + n)*HD_ + c0;
            #pragma unroll
            for (int j8 = 0; j8 < 8; j8++) {
                float y0 = (acc[mt][j8][ri*2]   + bb[j8][0]) * scale;
                float y1 = (acc[mt][j8][ri*2+1] + bb[j8][1]) * scale;
                *(__half2*)(dh + j8*8) = __floats2half2_rn(y0, y1);
            }
        }
    }
}

// ---------------- flash attention (R14 config: f16x2 exp + tensor-core l) ----------------
#define ATTN_SMEM 55296   // 3 stages * (K 9216 + V 9216)

__global__ __launch_bounds__(128, 4) void attn_kernel(float* __restrict__ out)
{
    extern __shared__ __align__(16) char sm[];
    const uint32_t smb = smem_u32(sm);
    const int tid = threadIdx.x, wid = tid >> 5, lane = tid & 31;
    const int q0 = blockIdx.x * 64;
    const int h = blockIdx.y, b = blockIdx.z;
    const size_t base = ((size_t)b*H_ + h) * N_ * HD_;
    const int r0 = lane >> 2, c0 = (lane & 3) * 2;

    // ---- persistent Q fragments (pre-scaled by log2e/8 in proj)
    uint32_t qf[4][4];
    {
        const __half* qh = g_Q + base + (size_t)(q0 + wid*16)*HD_;
        #pragma unroll
        for (int k = 0; k < 4; k++) {
            const int off = r0*64 + k*16 + c0;
            qf[k][0] = *(const uint32_t*)(qh + off);
            qf[k][1] = *(const uint32_t*)(qh + off + 8*64);
            qf[k][2] = *(const uint32_t*)(qh + off + 8);
            qf[k][3] = *(const uint32_t*)(qh + off + 8*64 + 8);
        }
    }

    // cp.async mapping: 128 threads, 512 16B-chunks per array -> 4 each
    uint32_t sA[4]; uint32_t gOf[4];
    #pragma unroll
    for (int j = 0; j < 4; j++) {
        const int idx = tid + j*128;
        const int row = idx >> 3, cc8 = (idx & 7) * 8;
        sA[j]  = (uint32_t)(row*72 + cc8) * 2;
        gOf[j] = (uint32_t)(row*64 + cc8);
    }
    const __half* gK = g_K + base;
    const __half* gV = g_V + base;

    // prologue: tiles 0 and 1 into stages 0,1
    #pragma unroll
    for (int st = 0; st < 2; st++) {
        const uint32_t sb = smb + st * 18432;
        const uint32_t ko = (uint32_t)st * 4096;
        #pragma unroll
        for (int j = 0; j < 4; j++) {
            CP16(sb + sA[j],        gK + ko + gOf[j]);
            CP16(sb + 9216 + sA[j], gV + ko + gOf[j]);
        }
        CP_COMMIT();
    }

    const uint32_t* m0p = g_mbits + ((size_t)b*N_ + q0 + wid*16 + r0) * 64;
    const uint32_t* m1p = m0p + 8*64;

    float o_acc[8][4] = {};
    float l_acc[4] = {};               // tensor-core row sums (ones-B)
    const uint32_t ONES = 0x3C003C00u; // fp16 {1.0, 1.0}

    const uint32_t tK = (uint32_t)(((((lane>>4)&1)*8 + (lane&7))*72 + ((lane>>3)&1)*8) * 2);
    const uint32_t tV = (uint32_t)(((((lane>>3)&1)*8 + (lane&7))*72 + ((lane>>4)&1)*8) * 2);

    for (int kt = 0; kt < 32; kt++) {
        if (kt == 31) { CP_WAIT0(); } else { CP_WAIT1(); }
        __syncthreads();

        // early mask loads (hide under MMAs)
        const uint2 w0 = *(const uint2*)(m0p + kt*2);
        const uint2 w1 = *(const uint2*)(m1p + kt*2);

        // prefetch tile kt+2 into stage (kt+2)%3
        if (kt < 30) {
            const uint32_t nb = smb + ((kt + 2) % 3) * 18432;
            const uint32_t koff = (uint32_t)(kt + 2) * 4096;
            #pragma unroll
            for (int j = 0; j < 4; j++) {
                CP16(nb + sA[j],        gK + koff + gOf[j]);
                CP16(nb + 9216 + sA[j], gV + koff + gOf[j]);
            }
            CP_COMMIT();
        }

        const uint32_t cb = smb + (kt % 3) * 18432;

        // ---- S = Q K^T
        float s[8][4] = {};
        {
            const uint32_t Kh = cb;
            #pragma unroll
            for (int k = 0; k < 4; k++) {
                #pragma unroll
                for (int jp = 0; jp < 4; jp++) {
                    const uint32_t addr = tK + jp*2304 + k*32;
                    uint32_t h0,h1,h2,h3;
                    LDSM4(h0,h1,h2,h3, Kh + addr);
                    MMA16816(s[2*jp],   qf[k][0],qf[k][1],qf[k][2],qf[k][3], h0,h1);
                    MMA16816(s[2*jp+1], qf[k][0],qf[k][1],qf[k][2],qf[k][3], h2,h3);
                }
            }
        }

        // ---- softmax: packed fp16 ex2 + bitwise mask
        uint32_t pa[8][2];
        #pragma unroll
        for (int j = 0; j < 8; j++) {
            const uint32_t wa = (j < 4) ? w0.x : w0.y;
            const uint32_t wb = (j < 4) ? w1.x : w1.y;
            const int sh = (j*8 + c0) & 31;
            uint32_t q01, q23, e01, e23;
            CVTF16X2(q01, s[j][1], s[j][0]);
            CVTF16X2(q23, s[j][3], s[j][2]);
            EX2H2(e01, q01);
            EX2H2(e23, q23);
            const uint32_t m01 = ((wa >> sh) & 1u) * 0x0000FFFFu
                               | ((wa >> (sh+1)) & 1u) * 0xFFFF0000u;
            const uint32_t m23 = ((wb >> sh) & 1u) * 0x0000FFFFu
                               | ((wb >> (sh+1)) & 1u) * 0xFFFF0000u;
            pa[j][0] = e01 & m01;
            pa[j][1] = e23 & m23;
        }

        // ---- O += P V ; l += P * ones (tensor-core row sum)
        {
            const uint32_t Vh = cb + 9216;
            #pragma unroll
            for (int t = 0; t < 4; t++) {
                const uint32_t a0 = pa[2*t][0],   a1 = pa[2*t][1];
                const uint32_t a2 = pa[2*t+1][0], a3 = pa[2*t+1][1];
                MMA16816(l_acc, a0,a1,a2,a3, ONES, ONES);
                #pragma unroll
                for (int jp = 0; jp < 4; jp++) {
                    const uint32_t addr = tV + t*2304 + jp*32;
                    uint32_t v0,v1,v2,v3;
                    LDSM4T(v0,v1,v2,v3, Vh + addr);
                    MMA16816(o_acc[2*jp],   a0,a1,a2,a3, v0,v1);
                    MMA16816(o_acc[2*jp+1], a0,a1,a2,a3, v2,v3);
                }
            }
        }
    }

    const float inv0 = 1.0f / l_acc[0], inv1 = 1.0f / l_acc[2];

    const int row0 = q0 + wid*16 + r0;
    float* d0 = out + ((size_t)b*N_ + row0) * DOUT_ + h*HD_ + c0;
    float* d1 = d0 + 8 * DOUT_;
    #pragma unroll
    for (int jo = 0; jo < 8; jo++) {
        float a0 = o_acc[jo][0] * inv0, a1 = o_acc[jo][1] * inv0;
        float a2 = o_acc[jo][2] * inv1, a3 = o_acc[jo][3] * inv1;
        float2 u0, u1;
        u0.x = (a0 > 0.f) ? a0 : expm1f(a0);
        u0.y = (a1 > 0.f) ? a1 : expm1f(a1);
        u1.x = (a2 > 0.f) ? a2 : expm1f(a2);
        u1.y = (a3 > 0.f) ? a3 : expm1f(a3);
        *(float2*)(d0 + jo*8) = u0;
        *(float2*)(d1 + jo*8) = u1;
    }
}

// ---------------- launch ----------------
extern "C" void kernel_launch(void* const* d_in, const int* in_sizes, int n_in,
                              void* d_out, int out_size)
{
    const float* x  = (const float*)d_in[0];
    const float* Wq = (const float*)d_in[1];
    const float* bq = (const float*)d_in[2];
    const float* Wk = (const float*)d_in[3];
    const float* bk = (const float*)d_in[4];
    const float* Wv = (const float*)d_in[5];
    const float* bv = (const float*)d_in[6];
    const int*   mask = (const int*)d_in[7];
    float* out = (float*)d_out;

    prep_all<<<PREP_TOTAL_BLOCKS, 256>>>(x, Wq, Wk, Wv, mask);

    cudaFuncSetAttribute(proj_kernel, cudaFuncAttributeMaxDynamicSharedMemorySize, PROJ_SMEM);
    proj_kernel<<<dim3((B_*N_)/128, DOUT_/128, 3), 256, PROJ_SMEM>>>(bq, bk, bv);

    cudaFuncSetAttribute(attn_kernel, cudaFuncAttributeMaxDynamicSharedMemorySize, ATTN_SMEM);
    attn_kernel<<<dim3(N_/64, H_, B_), 128, ATTN_SMEM>>>(out);
}